// round 2
// baseline (speedup 1.0000x reference)
#include <cuda_runtime.h>

#define NQ   4
#define DIM  16
#define NL   2
#define EDIM 512
#define E4   (EDIM/4)
#define NTHREADS 128
#define TOK_PER_WARP 32
#define TOK_PER_BLOCK 128
#define NTOKENS (512*128)

__global__ __launch_bounds__(NTHREADS)
void qlayer_fused(const float* __restrict__ x,
                  const float* __restrict__ qw,
                  const float* __restrict__ Wq,
                  const float* __restrict__ bq,
                  const float* __restrict__ Wc,
                  const float* __restrict__ bc,
                  float* __restrict__ out)
{
    __shared__ float4 sWq[NQ][E4];     // Wq[q][e]
    __shared__ float4 sWcT[NQ][E4];    // Wc transposed [q][e]
    __shared__ float4 sbc4[E4];
    __shared__ float2 sdiag[NL][DIM];  // fused CRZ-ring diagonal per layer
    __shared__ float2 srys[NL][NQ];    // (cos, sin) of theta/2 per RY
    __shared__ float  sbq[NQ];
    __shared__ float4 sqout[TOK_PER_BLOCK];

    const int tid  = threadIdx.x;
    const int lane = tid & 31;
    const int warp = tid >> 5;

    // ---- Stage weights / constants into shared ----
    for (int i = tid; i < NQ*E4; i += NTHREADS)
        ((float4*)sWq)[i] = ((const float4*)Wq)[i];
    {
        float* f = (float*)sWcT;
        for (int e = tid; e < EDIM; e += NTHREADS) {
            float4 r = ((const float4*)Wc)[e];
            f[0*EDIM+e] = r.x; f[1*EDIM+e] = r.y;
            f[2*EDIM+e] = r.z; f[3*EDIM+e] = r.w;
        }
    }
    for (int i = tid; i < E4; i += NTHREADS)
        sbc4[i] = ((const float4*)bc)[i];
    if (tid < NQ) sbq[tid] = bq[tid];

    if (tid < NL*DIM) {           // combined CRZ-ring diagonal
        int l = tid >> 4, k = tid & 15;
        float ang = 0.f;
        #pragma unroll
        for (int i = 0; i < NQ; i++) {
            int cb = (k >> (NQ-1-i)) & 1;
            int tb = (k >> (NQ-1-((i+1)&(NQ-1)))) & 1;
            if (cb) ang += 0.5f * qw[l*2*NQ + i] * (float)(2*tb - 1);
        }
        float sn, cs; sincosf(ang, &sn, &cs);
        sdiag[l][k] = make_float2(cs, sn);
    }
    if (tid >= 32 && tid < 32 + NL*NQ) {
        int t = tid - 32, l = t >> 2, i = t & 3;
        float sn, cs; sincosf(0.5f * qw[l*2*NQ + NQ + i], &sn, &cs);
        srys[l][i] = make_float2(cs, sn);
    }
    __syncthreads();   // only barrier in the kernel

    const int tokW = blockIdx.x * TOK_PER_BLOCK + warp * TOK_PER_WARP;
    const float bq0 = sbq[0], bq1 = sbq[1], bq2 = sbq[2], bq3 = sbq[3];

    // ---- Phase 1: q_in for 32 tokens/warp; groups of 4; tree reduce ----
    float4 qin;   // this lane's token's angles (set exactly once, group g == lane>>2)
    #pragma unroll 1
    for (int g = 0; g < 8; g++) {
        float v16[16];
        #pragma unroll
        for (int i = 0; i < 16; i++) v16[i] = 0.f;

        #pragma unroll
        for (int chunk = 0; chunk < 4; chunk++) {
            const int j4 = chunk*32 + lane;
            const float4 w0 = sWq[0][j4], w1 = sWq[1][j4];
            const float4 w2 = sWq[2][j4], w3 = sWq[3][j4];
            #pragma unroll
            for (int t = 0; t < 4; t++) {
                float4 xv = __ldcs(&((const float4*)x)[(size_t)(tokW + 4*g + t)*E4 + j4]);
                v16[4*t+0] += xv.x*w0.x + xv.y*w0.y + xv.z*w0.z + xv.w*w0.w;
                v16[4*t+1] += xv.x*w1.x + xv.y*w1.y + xv.z*w1.z + xv.w*w1.w;
                v16[4*t+2] += xv.x*w2.x + xv.y*w2.y + xv.z*w2.z + xv.w*w2.w;
                v16[4*t+3] += xv.x*w3.x + xv.y*w3.y + xv.z*w3.z + xv.w*w3.w;
            }
        }
        // multi-value tree reduction: 16 values -> 1 per lane in 16 SHFL
        float v8[8];
        {
            const bool hi = (lane & 16) != 0;
            #pragma unroll
            for (int i = 0; i < 8; i++) {
                float mine = hi ? v16[i+8] : v16[i];
                float send = hi ? v16[i]   : v16[i+8];
                v8[i] = mine + __shfl_xor_sync(0xffffffffu, send, 16);
            }
        }
        float v4[4];
        {
            const bool hi = (lane & 8) != 0;
            #pragma unroll
            for (int i = 0; i < 4; i++) {
                float mine = hi ? v8[i+4] : v8[i];
                float send = hi ? v8[i]   : v8[i+4];
                v4[i] = mine + __shfl_xor_sync(0xffffffffu, send, 8);
            }
        }
        float v2[2];
        {
            const bool hi = (lane & 4) != 0;
            #pragma unroll
            for (int i = 0; i < 2; i++) {
                float mine = hi ? v4[i+2] : v4[i];
                float send = hi ? v4[i]   : v4[i+2];
                v2[i] = mine + __shfl_xor_sync(0xffffffffu, send, 4);
            }
        }
        float v1;
        {
            const bool hi = (lane & 2) != 0;
            float mine = hi ? v2[1] : v2[0];
            float send = hi ? v2[0] : v2[1];
            v1 = mine + __shfl_xor_sync(0xffffffffu, send, 2);
        }
        v1 += __shfl_xor_sync(0xffffffffu, v1, 1);
        // lane L now holds (t = L>>3, q = 2*((L>>2)&1) + ((L>>1)&1)); gather to dest lanes
        const int tl = lane & 3;
        float gx = __shfl_sync(0xffffffffu, v1, 8*tl + 0);
        float gy = __shfl_sync(0xffffffffu, v1, 8*tl + 2);
        float gz = __shfl_sync(0xffffffffu, v1, 8*tl + 4);
        float gw = __shfl_sync(0xffffffffu, v1, 8*tl + 6);
        if ((lane >> 2) == g)
            qin = make_float4(gx + bq0, gy + bq1, gz + bq2, gw + bq3);
    }

    // ---- Phase 2: 4-qubit circuit, one token per lane (all 32 lanes busy) ----
    {
        float c[4], s[4];
        __sincosf(0.5f*qin.x, &s[0], &c[0]);
        __sincosf(0.5f*qin.y, &s[1], &c[1]);
        __sincosf(0.5f*qin.z, &s[2], &c[2]);
        __sincosf(0.5f*qin.w, &s[3], &c[3]);

        float2 st[DIM];
        #pragma unroll
        for (int k = 0; k < DIM; k++) {
            float m = 1.f; int p = 0;
            #pragma unroll
            for (int w = 0; w < NQ; w++) {
                if ((k >> (NQ-1-w)) & 1) { m *= s[w]; p++; }
                else                     { m *= c[w]; }
            }
            float re, im;
            switch (p & 3) {
                case 0:  re =  m; im = 0.f; break;
                case 1:  re = 0.f; im = -m; break;
                case 2:  re = -m; im = 0.f; break;
                default: re = 0.f; im =  m; break;
            }
            st[k] = make_float2(re, im);
        }

        #pragma unroll
        for (int l = 0; l < NL; l++) {
            #pragma unroll
            for (int k = 0; k < DIM; k++) {
                float2 d = sdiag[l][k];
                float re = st[k].x*d.x - st[k].y*d.y;
                float im = st[k].x*d.y + st[k].y*d.x;
                st[k].x = re; st[k].y = im;
            }
            #pragma unroll
            for (int i = 0; i < NQ; i++) {
                float2 cs = srys[l][i];
                const int S = 1 << (NQ-1-i);
                #pragma unroll
                for (int k = 0; k < DIM; k++) {
                    if (k & S) continue;
                    float2 a0 = st[k], a1 = st[k|S];
                    st[k].x   = cs.x*a0.x - cs.y*a1.x;
                    st[k].y   = cs.x*a0.y - cs.y*a1.y;
                    st[k|S].x = cs.y*a0.x + cs.x*a1.x;
                    st[k|S].y = cs.y*a0.y + cs.x*a1.y;
                }
            }
        }

        float z0=0.f, z1=0.f, z2=0.f, z3=0.f;
        #pragma unroll
        for (int k = 0; k < DIM; k++) {
            float p = st[k].x*st[k].x + st[k].y*st[k].y;
            z0 += (k & 8) ? -p : p;
            z1 += (k & 4) ? -p : p;
            z2 += (k & 2) ? -p : p;
            z3 += (k & 1) ? -p : p;
        }
        sqout[warp*TOK_PER_WARP + lane] = make_float4(z0, z1, z2, z3);
    }
    __syncwarp();

    // ---- Phase 3: out = q_out . Wc^T + bc (coalesced streaming stores) ----
    #pragma unroll 1
    for (int chunk = 0; chunk < 4; chunk++) {
        const int e4 = chunk*32 + lane;
        const float4 w0 = sWcT[0][e4], w1 = sWcT[1][e4];
        const float4 w2 = sWcT[2][e4], w3 = sWcT[3][e4];
        const float4 b  = sbc4[e4];
        #pragma unroll 4
        for (int m = 0; m < TOK_PER_WARP; m++) {
            float4 qo = sqout[warp*TOK_PER_WARP + m];   // LDS broadcast
            float4 o;
            o.x = b.x + qo.x*w0.x + qo.y*w1.x + qo.z*w2.x + qo.w*w3.x;
            o.y = b.y + qo.x*w0.y + qo.y*w1.y + qo.z*w2.y + qo.w*w3.y;
            o.z = b.z + qo.x*w0.z + qo.y*w1.z + qo.z*w2.z + qo.w*w3.z;
            o.w = b.w + qo.x*w0.w + qo.y*w1.w + qo.z*w2.w + qo.w*w3.w;
            __stcs(&((float4*)out)[(size_t)(tokW + m)*E4 + e4], o);
        }
    }
}

extern "C" void kernel_launch(void* const* d_in, const int* in_sizes, int n_in,
                              void* d_out, int out_size) {
    const float* x  = (const float*)d_in[0];
    const float* qw = (const float*)d_in[1];
    const float* Wq = (const float*)d_in[2];
    const float* bq = (const float*)d_in[3];
    const float* Wc = (const float*)d_in[4];
    const float* bc = (const float*)d_in[5];
    float* out = (float*)d_out;

    dim3 grid(NTOKENS / TOK_PER_BLOCK);   // 512 blocks x 128 threads
    qlayer_fused<<<grid, NTHREADS>>>(x, qw, Wq, bq, Wc, bc, out);
}

// round 3
// speedup vs baseline: 1.2311x; 1.2311x over previous
#include <cuda_runtime.h>

#define NQ   4
#define DIM  16
#define NL   2
#define EDIM 512
#define E4   (EDIM/4)
#define NTHREADS 128
#define TOK_PER_WARP 8
#define TOK_PER_BLOCK 32
#define NTOKENS (512*128)

__global__ __launch_bounds__(NTHREADS, 8)
void qlayer_fused(const float* __restrict__ x,
                  const float* __restrict__ qw,
                  const float* __restrict__ Wq,
                  const float* __restrict__ bq,
                  const float* __restrict__ Wc,
                  const float* __restrict__ bc,
                  float* __restrict__ out)
{
    __shared__ float4 sWq[NQ][E4];     // Wq[q][e]
    __shared__ float4 sWcT[NQ][E4];    // Wc transposed [q][e]
    __shared__ float4 sbc4[E4];
    __shared__ float2 sdiag[NL][DIM];  // fused CRZ-ring diagonal per layer
    __shared__ float2 srys[NL][NQ];    // (cos, sin) of theta/2 per RY
    __shared__ float  sbq[NQ];
    __shared__ float4 sqout[TOK_PER_BLOCK];

    const int tid  = threadIdx.x;
    const int lane = tid & 31;
    const int warp = tid >> 5;

    // ---- Stage weights / constants into shared ----
    for (int i = tid; i < NQ*E4; i += NTHREADS)
        ((float4*)sWq)[i] = ((const float4*)Wq)[i];
    {
        float* f = (float*)sWcT;
        for (int e = tid; e < EDIM; e += NTHREADS) {
            float4 r = ((const float4*)Wc)[e];
            f[0*EDIM+e] = r.x; f[1*EDIM+e] = r.y;
            f[2*EDIM+e] = r.z; f[3*EDIM+e] = r.w;
        }
    }
    for (int i = tid; i < E4; i += NTHREADS)
        sbc4[i] = ((const float4*)bc)[i];
    if (tid < NQ) sbq[tid] = bq[tid];

    if (tid < NL*DIM) {           // combined CRZ-ring diagonal
        int l = tid >> 4, k = tid & 15;
        float ang = 0.f;
        #pragma unroll
        for (int i = 0; i < NQ; i++) {
            int cb = (k >> (NQ-1-i)) & 1;
            int tb = (k >> (NQ-1-((i+1)&(NQ-1)))) & 1;
            if (cb) ang += 0.5f * qw[l*2*NQ + i] * (float)(2*tb - 1);
        }
        float sn, cs; sincosf(ang, &sn, &cs);
        sdiag[l][k] = make_float2(cs, sn);
    }
    if (tid >= 32 && tid < 32 + NL*NQ) {
        int t = tid - 32, l = t >> 2, i = t & 3;
        float sn, cs; sincosf(0.5f * qw[l*2*NQ + NQ + i], &sn, &cs);
        srys[l][i] = make_float2(cs, sn);
    }
    __syncthreads();   // only block barrier

    const int tokW = blockIdx.x * TOK_PER_BLOCK + warp * TOK_PER_WARP;
    const float bq0 = sbq[0], bq1 = sbq[1], bq2 = sbq[2], bq3 = sbq[3];

    // ---- Phase 1: q_in for 8 tokens/warp; 2 groups of 4; tree reduce ----
    float4 qin;   // valid on lanes 0..7 (one token per lane)
    #pragma unroll 1
    for (int g = 0; g < 2; g++) {
        float v16[16];
        #pragma unroll
        for (int i = 0; i < 16; i++) v16[i] = 0.f;

        #pragma unroll
        for (int chunk = 0; chunk < 4; chunk++) {
            const int j4 = chunk*32 + lane;
            const float4 w0 = sWq[0][j4], w1 = sWq[1][j4];
            const float4 w2 = sWq[2][j4], w3 = sWq[3][j4];
            #pragma unroll
            for (int t = 0; t < 4; t++) {
                float4 xv = __ldcs(&((const float4*)x)[(size_t)(tokW + 4*g + t)*E4 + j4]);
                v16[4*t+0] += xv.x*w0.x + xv.y*w0.y + xv.z*w0.z + xv.w*w0.w;
                v16[4*t+1] += xv.x*w1.x + xv.y*w1.y + xv.z*w1.z + xv.w*w1.w;
                v16[4*t+2] += xv.x*w2.x + xv.y*w2.y + xv.z*w2.z + xv.w*w2.w;
                v16[4*t+3] += xv.x*w3.x + xv.y*w3.y + xv.z*w3.z + xv.w*w3.w;
            }
        }
        // multi-value tree reduction: 16 values -> 1 per lane
        float v8[8];
        {
            const bool hi = (lane & 16) != 0;
            #pragma unroll
            for (int i = 0; i < 8; i++) {
                float mine = hi ? v16[i+8] : v16[i];
                float send = hi ? v16[i]   : v16[i+8];
                v8[i] = mine + __shfl_xor_sync(0xffffffffu, send, 16);
            }
        }
        float v4[4];
        {
            const bool hi = (lane & 8) != 0;
            #pragma unroll
            for (int i = 0; i < 4; i++) {
                float mine = hi ? v8[i+4] : v8[i];
                float send = hi ? v8[i]   : v8[i+4];
                v4[i] = mine + __shfl_xor_sync(0xffffffffu, send, 8);
            }
        }
        float v2[2];
        {
            const bool hi = (lane & 4) != 0;
            #pragma unroll
            for (int i = 0; i < 2; i++) {
                float mine = hi ? v2[0]*0.f + (hi ? v4[i+2] : v4[i]) : v4[i]; // placeholder avoided below
                (void)mine;
            }
            // (clean version)
            #pragma unroll
            for (int i = 0; i < 2; i++) {
                float m2 = hi ? v4[i+2] : v4[i];
                float s2 = hi ? v4[i]   : v4[i+2];
                v2[i] = m2 + __shfl_xor_sync(0xffffffffu, s2, 4);
            }
        }
        float v1;
        {
            const bool hi = (lane & 2) != 0;
            float mine = hi ? v2[1] : v2[0];
            float send = hi ? v2[0] : v2[1];
            v1 = mine + __shfl_xor_sync(0xffffffffu, send, 2);
        }
        v1 += __shfl_xor_sync(0xffffffffu, v1, 1);
        // lane L holds (t = L>>3, q = 2*((L>>2)&1) + ((L>>1)&1)); gather to lanes 4g..4g+3
        const int tl = lane & 3;
        float gx = __shfl_sync(0xffffffffu, v1, 8*tl + 0);
        float gy = __shfl_sync(0xffffffffu, v1, 8*tl + 2);
        float gz = __shfl_sync(0xffffffffu, v1, 8*tl + 4);
        float gw = __shfl_sync(0xffffffffu, v1, 8*tl + 6);
        if ((lane >> 2) == g)
            qin = make_float4(gx + bq0, gy + bq1, gz + bq2, gw + bq3);
    }

    // ---- Phase 2: 4-qubit circuit, lanes 0..7 (one token per lane) ----
    if (lane < TOK_PER_WARP) {
        float c[4], s[4];
        __sincosf(0.5f*qin.x, &s[0], &c[0]);
        __sincosf(0.5f*qin.y, &s[1], &c[1]);
        __sincosf(0.5f*qin.z, &s[2], &c[2]);
        __sincosf(0.5f*qin.w, &s[3], &c[3]);

        float2 st[DIM];
        #pragma unroll
        for (int k = 0; k < DIM; k++) {
            float m = 1.f; int p = 0;
            #pragma unroll
            for (int w = 0; w < NQ; w++) {
                if ((k >> (NQ-1-w)) & 1) { m *= s[w]; p++; }
                else                     { m *= c[w]; }
            }
            float re, im;
            switch (p & 3) {
                case 0:  re =  m; im = 0.f; break;
                case 1:  re = 0.f; im = -m; break;
                case 2:  re = -m; im = 0.f; break;
                default: re = 0.f; im =  m; break;
            }
            st[k] = make_float2(re, im);
        }

        #pragma unroll
        for (int l = 0; l < NL; l++) {
            #pragma unroll
            for (int k = 0; k < DIM; k++) {
                float2 d = sdiag[l][k];
                float re = st[k].x*d.x - st[k].y*d.y;
                float im = st[k].x*d.y + st[k].y*d.x;
                st[k].x = re; st[k].y = im;
            }
            #pragma unroll
            for (int i = 0; i < NQ; i++) {
                float2 cs = srys[l][i];
                const int S = 1 << (NQ-1-i);
                #pragma unroll
                for (int k = 0; k < DIM; k++) {
                    if (k & S) continue;
                    float2 a0 = st[k], a1 = st[k|S];
                    st[k].x   = cs.x*a0.x - cs.y*a1.x;
                    st[k].y   = cs.x*a0.y - cs.y*a1.y;
                    st[k|S].x = cs.y*a0.x + cs.x*a1.x;
                    st[k|S].y = cs.y*a0.y + cs.x*a1.y;
                }
            }
        }

        float z0=0.f, z1=0.f, z2=0.f, z3=0.f;
        #pragma unroll
        for (int k = 0; k < DIM; k++) {
            float p = st[k].x*st[k].x + st[k].y*st[k].y;
            z0 += (k & 8) ? -p : p;
            z1 += (k & 4) ? -p : p;
            z2 += (k & 2) ? -p : p;
            z3 += (k & 1) ? -p : p;
        }
        sqout[warp*TOK_PER_WARP + lane] = make_float4(z0, z1, z2, z3);
    }
    __syncwarp();

    // ---- Phase 3: out = q_out . Wc^T + bc (coalesced streaming stores) ----
    #pragma unroll 1
    for (int chunk = 0; chunk < 4; chunk++) {
        const int e4 = chunk*32 + lane;
        const float4 w0 = sWcT[0][e4], w1 = sWcT[1][e4];
        const float4 w2 = sWcT[2][e4], w3 = sWcT[3][e4];
        const float4 b  = sbc4[e4];
        #pragma unroll
        for (int m = 0; m < TOK_PER_WARP; m++) {
            float4 qo = sqout[warp*TOK_PER_WARP + m];   // LDS broadcast
            float4 o;
            o.x = b.x + qo.x*w0.x + qo.y*w1.x + qo.z*w2.x + qo.w*w3.x;
            o.y = b.y + qo.x*w0.y + qo.y*w1.y + qo.z*w2.y + qo.w*w3.y;
            o.z = b.z + qo.x*w0.z + qo.y*w1.z + qo.z*w2.z + qo.w*w3.z;
            o.w = b.w + qo.x*w0.w + qo.y*w1.w + qo.z*w2.w + qo.w*w3.w;
            __stcs(&((float4*)out)[(size_t)(tokW + m)*E4 + e4], o);
        }
    }
}

extern "C" void kernel_launch(void* const* d_in, const int* in_sizes, int n_in,
                              void* d_out, int out_size) {
    const float* x  = (const float*)d_in[0];
    const float* qw = (const float*)d_in[1];
    const float* Wq = (const float*)d_in[2];
    const float* bq = (const float*)d_in[3];
    const float* Wc = (const float*)d_in[4];
    const float* bc = (const float*)d_in[5];
    float* out = (float*)d_out;

    dim3 grid(NTOKENS / TOK_PER_BLOCK);   // 2048 blocks x 128 threads
    qlayer_fused<<<grid, NTHREADS>>>(x, qw, Wq, bq, Wc, bc, out);
}